// round 5
// baseline (speedup 1.0000x reference)
#include <cuda_runtime.h>
#include <math.h>

#define NEGV  (-1e30f)
#define LOG2E 1.4426950408889634f
#define LN2   0.6931471805599453f
#define MAXL  128
#define NPAIR (MAXL + 2)       // pairs 0..128 (+pad)
#define NW    6
#define BLOCK (NW * 32)        // 192 threads
#define OWN   24               // owned pairs per warp
#define HALO  8                // halo pairs == steps per round

__device__ float g_partial[256];
__device__ int   g_ctr = 0;

__device__ __forceinline__ float ex2f(float x) {
    float r; asm("ex2.approx.ftz.f32 %0, %1;" : "=f"(r) : "f"(x)); return r;
}
__device__ __forceinline__ float lg2f(float x) {
    float r; asm("lg2.approx.ftz.f32 %0, %1;" : "=f"(r) : "f"(x)); return r;
}

__global__ void __launch_bounds__(BLOCK, 1)
ctc_fwd(const float* __restrict__ lp,      // [T, B, V] log-probs (ln domain)
        const int*   __restrict__ targets, // [B, L]
        const int*   __restrict__ ilen,    // [B]
        float* __restrict__ out,
        int T, int B, int V, int L)
{
    const int b    = blockIdx.x;
    const int tid  = threadIdx.x;
    const int w    = tid >> 5;
    const int lane = tid & 31;

    __shared__ float sh_pa[2][NPAIR];     // even-state alpha per pair (double buf)
    __shared__ float sh_po[2][NPAIR];     // odd-state alpha per pair

    int Tb = ilen[b];
    if (Tb > T) Tb = T;

    // pair = 24*w + lane - 8  (lanes 0..7 of each warp are halo)
    const int  pair      = OWN * w + lane - HALO;          // -8 .. 135
    const int  jc        = min(max(pair, 0), L - 1);
    const bool odd_valid = (pair >= 0 && pair < L);
    const int  lab       = targets[b * L + jc];
    bool skip = false;
    if (pair >= 1 && pair < L) skip = (targets[b * L + pair - 1] != lab);

    const size_t strideT = (size_t)B * (size_t)V;
    const float* gb = lp + (size_t)b * (size_t)V;          // blank emission col
    const float* gl = gb + lab;                            // own label emission col

    // ---- register emission prefetch ring, depth 8 (times 0..7) ----
    float rb[8], rl[8];
    #pragma unroll
    for (int i = 0; i < 8; ++i) {
        const int tc = (i < Tb) ? i : 0;
        rb[i] = __ldg(gb + (size_t)tc * strideT);
        rl[i] = __ldg(gl + (size_t)tc * strideT);
    }
    const float* pb = gb + 8 * strideT;                    // rolling prefetch ptrs
    const float* pl = gl + 8 * strideT;

    // ---- t = 0 init (log2 domain): only states 0, 1 live ----
    float a_even = (pair == 0) ? rb[0] * LOG2E : NEGV;
    float a_odd  = (pair == 0) ? rl[0] * LOG2E : NEGV;

    // ---- rounds of 8 steps; ONE __syncthreads per round ----
    const int R = (Tb + 7) >> 3;
    for (int r = 0; r < R; ++r) {
        // halo refresh from previous round's published buffer
        if (r > 0 && lane < HALO && pair >= 0) {
            a_even = sh_pa[(r - 1) & 1][pair];
            a_odd  = sh_po[(r - 1) & 1][pair];
        }

        #pragma unroll
        for (int i = 0; i < 8; ++i) {
            const int t = 8 * r + i;

            const float eb = rb[i];
            const float el = rl[i];
            // prefetch time t+8 into the slot just consumed
            if (t + 8 < Tb) { rb[i] = __ldg(pb); rl[i] = __ldg(pl); }
            pb += strideT; pl += strideT;

            float po = __shfl_up_sync(0xFFFFFFFFu, a_odd, 1);  // alpha[2p-1]
            if (pair == 0) po = NEGV;

            // even state 2p <- {2p, 2p-1}
            const float me = fmaxf(a_even, po);
            float ne = me + lg2f(1.0f + ex2f(fminf(a_even, po) - me));
            ne = fmaf(eb, LOG2E, ne);

            // odd state 2p+1 <- {2p+1, 2p, 2p-1 if skip}
            const float a2 = skip ? po : NEGV;
            const float mo = fmaxf(fmaxf(a_odd, a_even), a2);
            float no = mo + lg2f(ex2f(a_odd - mo) + ex2f(a_even - mo) +
                                 ex2f(a2 - mo));
            no = fmaf(el, LOG2E, no);

            const bool live = (t >= 1) && (t < Tb);   // skip t=0; freeze past Tb
            a_even = live ? ne : a_even;
            a_odd  = live ? (odd_valid ? no : NEGV) : a_odd;
        }

        // publish owned pairs for next round's halo
        if (lane >= HALO && pair <= L) {
            sh_pa[r & 1][pair] = a_even;
            sh_po[r & 1][pair] = a_odd;
        }
        __syncthreads();
    }

    // final: state 255 = pair 127 odd (w5 lane15); state 256 = pair 128 even (w5 lane16)
    if (w == NW - 1) {
        const float v255 = __shfl_sync(0xFFFFFFFFu, a_odd,  15);
        const float v256 = __shfl_sync(0xFFFFFFFFu, a_even, 16);
        if (lane == 0) {
            const float m = fmaxf(v255, v256);
            g_partial[b] = (m + lg2f(1.0f + ex2f(fminf(v255, v256) - m))) * LN2;
        }
    }

    // ---- fused deterministic reduction: last CTA sums in fixed order ----
    __threadfence();
    __shared__ int s_last;
    if (tid == 0) s_last = (atomicAdd(&g_ctr, 1) == gridDim.x - 1) ? 1 : 0;
    __syncthreads();
    if (s_last && w == 0) {
        __threadfence();                    // acquire others' g_partial writes
        float v = 0.0f;
        for (int i = lane; i < B; i += 32) v += g_partial[i];
        #pragma unroll
        for (int off = 16; off > 0; off >>= 1)
            v += __shfl_down_sync(0xFFFFFFFFu, v, off);
        if (lane == 0) { out[0] = -v; g_ctr = 0; }   // reset for next replay
    }
}

extern "C" void kernel_launch(void* const* d_in, const int* in_sizes, int n_in,
                              void* d_out, int out_size)
{
    const float* lp      = (const float*)d_in[0];   // log_probs [T,B,V] f32
    const int*   targets = (const int*)  d_in[1];   // [B*L] i32
    const int*   ilen    = (const int*)  d_in[2];   // [B] i32
    // d_in[3] = target_lengths (all == L), unused

    const int B = in_sizes[2];
    const int L = in_sizes[1] / B;
    const int V = 1000;                              // fixed problem shape
    const int T = (int)((long long)in_sizes[0] / ((long long)B * V));

    ctc_fwd<<<B, BLOCK>>>(lp, targets, ilen, (float*)d_out, T, B, V, L);
}

// round 6
// speedup vs baseline: 1.6900x; 1.6900x over previous
#include <cuda_runtime.h>
#include <math.h>

#define NEGV  (-1e30f)
#define LOG2E 1.4426950408889634f
#define LN2   0.6931471805599453f
#define MAXL  128
#define NPAIR (MAXL + 2)       // pairs 0..128 (+pad)
#define NW    6
#define BLOCK (NW * 32)        // 192 threads
#define OWN   24               // owned pairs per warp
#define HALO  8                // halo pairs == steps per round
#define EROW  132              // floats per emission ring row (pad)
#define RSLOT 32               // ring slots (4 groups of 8)

__device__ float g_partial[256];
__device__ int   g_ctr = 0;

__device__ __forceinline__ float ex2f(float x) {
    float r; asm("ex2.approx.ftz.f32 %0, %1;" : "=f"(r) : "f"(x)); return r;
}
__device__ __forceinline__ float lg2f(float x) {
    float r; asm("lg2.approx.ftz.f32 %0, %1;" : "=f"(r) : "f"(x)); return r;
}
__device__ __forceinline__ unsigned smem_u32(const void* p) {
    return (unsigned)__cvta_generic_to_shared(p);
}
__device__ __forceinline__ void cp4(unsigned dst, const float* src) {
    asm volatile("cp.async.ca.shared.global [%0], [%1], 4;\n" :: "r"(dst), "l"(src));
}
__device__ __forceinline__ void cp_commit() { asm volatile("cp.async.commit_group;\n"); }
__device__ __forceinline__ void cp_wait2()  { asm volatile("cp.async.wait_group 2;\n"); }

__global__ void __launch_bounds__(BLOCK, 1)
ctc_fwd(const float* __restrict__ lp,      // [T, B, V] log-probs (ln domain)
        const int*   __restrict__ targets, // [B, L]
        const int*   __restrict__ ilen,    // [B]
        float* __restrict__ out,
        int T, int B, int V, int L)
{
    const int b    = blockIdx.x;
    const int tid  = threadIdx.x;
    const int w    = tid >> 5;
    const int lane = tid & 31;

    __shared__ float sh_e[RSLOT][EROW];   // [slot][0]=blank, [1+j]=label j (ln domain)
    __shared__ float sh_pa[2][NPAIR];     // even-state alpha per pair (double buf)
    __shared__ float sh_po[2][NPAIR];     // odd-state alpha per pair

    int Tb = ilen[b];
    if (Tb > T) Tb = T;

    // pair = 24*w + lane - 8  (lanes 0..7 of each warp are halo)
    const int  pair      = OWN * w + lane - HALO;          // -8 .. 135
    const int  jc        = min(max(pair, 0), L - 1);
    const bool odd_valid = (pair >= 0 && pair < L);
    const int  lab       = targets[b * L + jc];
    bool skip = false;
    if (pair >= 1 && pair < L) skip = (targets[b * L + pair - 1] != lab);

    // ---- loader role: tid<L loads label tid's emission, tid==L loads blank ----
    const bool loader = (tid <= L);
    const float* gsrc = nullptr;
    unsigned dst0 = 0;
    if (loader) {
        const int vv = (tid < L) ? targets[b * L + tid] : 0;
        const int ee = (tid < L) ? (tid + 1)            : 0;
        gsrc = lp + (size_t)b * (size_t)V + vv;
        dst0 = smem_u32(&sh_e[0][ee]);
    }
    const size_t   strideT = (size_t)B * (size_t)V;
    const unsigned rowB    = EROW * sizeof(float);

    // ---- prologue: issue emission groups 0..2 (times 0..23), 3 groups in flight
    #pragma unroll
    for (int g = 0; g < 3; ++g) {
        if (loader) {
            #pragma unroll
            for (int i = 0; i < 8; ++i) {
                const int t = 8 * g + i;
                if (t < Tb) cp4(dst0 + (unsigned)(t & (RSLOT - 1)) * rowB,
                                gsrc + (size_t)t * strideT);
            }
        }
        cp_commit();
    }
    cp_wait2();          // group 0 complete
    __syncthreads();

    // ---- alpha at t=0 (log2 domain): only states 0, 1 live ----
    float a_even = NEGV, a_odd = NEGV;
    if (pair == 0) { a_even = sh_e[0][0] * LOG2E; a_odd = sh_e[0][1] * LOG2E; }

    // ---- rounds of 8 steps; ONE __syncthreads per round ----
    const int R = (Tb + 7) >> 3;
    for (int r = 0; r < R; ++r) {
        // halo refresh from previous round's published buffer
        if (r > 0 && lane < HALO && pair >= 0) {
            a_even = sh_pa[(r - 1) & 1][pair];
            a_odd  = sh_po[(r - 1) & 1][pair];
        }

        // preload this round's emissions to registers (group r is complete)
        float eb[8], el[8];
        #pragma unroll
        for (int i = 0; i < 8; ++i) {
            const int slot = (8 * r + i) & (RSLOT - 1);
            eb[i] = sh_e[slot][0];
            el[i] = sh_e[slot][1 + jc];
        }

        const int tg = 8 * (r + 3);   // prefetch group (3 rounds ahead)
        #pragma unroll
        for (int i = 0; i < 8; ++i) {
            const int t = 8 * r + i;
            if (loader && (tg + i) < Tb)
                cp4(dst0 + (unsigned)((tg + i) & (RSLOT - 1)) * rowB,
                    gsrc + (size_t)(tg + i) * strideT);

            float po = __shfl_up_sync(0xFFFFFFFFu, a_odd, 1);  // alpha[2p-1]
            if (pair == 0) po = NEGV;

            // joint max over the three incoming values
            const float q = fmaxf(a_even, a_odd);   // off the po-chain
            const float m = fmaxf(q, po);
            const float x = ex2f(a_even - m);
            const float z = ex2f(a_odd  - m);
            const float y = ex2f(po     - m);

            // even state 2p <- {2p, 2p-1};  odd 2p+1 <- {2p+1, 2p, 2p-1 if skip}
            float ne = fmaf(eb[i], LOG2E, m + lg2f(x + y));
            float no = fmaf(el[i], LOG2E, m + lg2f((x + z) + (skip ? y : 0.0f)));
            ne = fmaxf(ne, NEGV);                   // clamp -inf (NaN safety)
            no = fmaxf(no, NEGV);

            const bool live = (t >= 1) && (t < Tb); // skip t=0; freeze past Tb
            a_even = live ? ne : a_even;
            a_odd  = live ? (odd_valid ? no : NEGV) : a_odd;
        }

        // publish owned pairs for next round's halo
        if (lane >= HALO && pair <= L) {
            sh_pa[r & 1][pair] = a_even;
            sh_po[r & 1][pair] = a_odd;
        }
        cp_commit();
        cp_wait2();       // next round's emission group complete
        __syncthreads();
    }

    // final: state 255 = pair 127 odd (w5 lane15); state 256 = pair 128 even (w5 lane16)
    if (w == NW - 1) {
        const float v255 = __shfl_sync(0xFFFFFFFFu, a_odd,  15);
        const float v256 = __shfl_sync(0xFFFFFFFFu, a_even, 16);
        if (lane == 0) {
            const float m = fmaxf(v255, v256);
            g_partial[b] = (m + lg2f(1.0f + ex2f(fminf(v255, v256) - m))) * LN2;
        }
    }

    // ---- fused deterministic reduction: last CTA sums in fixed order ----
    __threadfence();
    __shared__ int s_last;
    if (tid == 0) s_last = (atomicAdd(&g_ctr, 1) == gridDim.x - 1) ? 1 : 0;
    __syncthreads();
    if (s_last && w == 0) {
        __threadfence();                    // acquire others' g_partial writes
        float v = 0.0f;
        for (int i = lane; i < B; i += 32) v += g_partial[i];
        #pragma unroll
        for (int off = 16; off > 0; off >>= 1)
            v += __shfl_down_sync(0xFFFFFFFFu, v, off);
        if (lane == 0) { out[0] = -v; g_ctr = 0; }   // reset for next replay
    }
}

extern "C" void kernel_launch(void* const* d_in, const int* in_sizes, int n_in,
                              void* d_out, int out_size)
{
    const float* lp      = (const float*)d_in[0];   // log_probs [T,B,V] f32
    const int*   targets = (const int*)  d_in[1];   // [B*L] i32
    const int*   ilen    = (const int*)  d_in[2];   // [B] i32
    // d_in[3] = target_lengths (all == L), unused

    const int B = in_sizes[2];
    const int L = in_sizes[1] / B;
    const int V = 1000;                              // fixed problem shape
    const int T = (int)((long long)in_sizes[0] / ((long long)B * V));

    ctc_fwd<<<B, BLOCK>>>(lp, targets, ilen, (float*)d_out, T, B, V, L);
}

// round 7
// speedup vs baseline: 2.7821x; 1.6462x over previous
#include <cuda_runtime.h>
#include <math.h>

#define NEGV  (-1e30f)
#define LOG2E 1.4426950408889634f
#define LN2   0.6931471805599453f
#define MAXL  128
#define NPAIR (MAXL + 2)
#define NW    6
#define BLOCK (NW * 32)        // 192 threads
#define OWN   24
#define HALO  8
#define EROW  132
#define RSLOT 32
#define MAXB  64

__device__ float g_partial[MAXB];
__device__ float g_bt[MAXB][260];     // bt(tm+1, s) natural order; [257..259] = pad
__device__ int   g_flag[MAXB];        // zero-init; backward sets, forward resets
__device__ int   g_ctr = 0;

__device__ __forceinline__ float ex2f(float x) {
    float r; asm("ex2.approx.ftz.f32 %0, %1;" : "=f"(r) : "f"(x)); return r;
}
__device__ __forceinline__ float lg2f(float x) {
    float r; asm("lg2.approx.ftz.f32 %0, %1;" : "=f"(r) : "f"(x)); return r;
}
__device__ __forceinline__ float lse2(float a, float b) {   // log2 domain
    float m = fmaxf(a, b);
    return m + lg2f(1.0f + ex2f(fminf(a, b) - m));
}
__device__ __forceinline__ unsigned smem_u32(const void* p) {
    return (unsigned)__cvta_generic_to_shared(p);
}
__device__ __forceinline__ void cp4(unsigned dst, const float* src) {
    asm volatile("cp.async.ca.shared.global [%0], [%1], 4;\n" :: "r"(dst), "l"(src));
}
__device__ __forceinline__ void cp_commit() { asm volatile("cp.async.commit_group;\n"); }
__device__ __forceinline__ void cp_wait2()  { asm volatile("cp.async.wait_group 2;\n"); }

__global__ void __launch_bounds__(BLOCK, 1)
ctc_bidir(const float* __restrict__ lp,      // [T, B, V] log-probs (ln domain)
          const int*   __restrict__ targets, // [B, L]
          const int*   __restrict__ ilen,    // [B]
          float* __restrict__ out,
          int T, int B, int V, int L)
{
    const int b    = blockIdx.x >> 1;
    const int dir  = blockIdx.x & 1;          // 0 = forward, 1 = backward
    const int tid  = threadIdx.x;
    const int w    = tid >> 5;
    const int lane = tid & 31;

    __shared__ float sh_e[RSLOT][EROW];
    __shared__ float sh_pa[2][NPAIR];
    __shared__ float sh_po[2][NPAIR];
    __shared__ float sh_red[NW];

    int Tb = ilen[b];
    if (Tb > T) Tb = T;
    const int tm = Tb >> 1;
    const int N  = dir ? (Tb - tm - 2) : tm;  // live steps k = 1..N

    // pair = 24*w + lane - 8 (lanes 0..7 halo).  dir1 works in reflected coords.
    const int  pair      = OWN * w + lane - HALO;          // -8 .. 135
    const int  jq        = dir ? (127 - pair) : pair;      // label index of own odd state
    const int  jc        = min(max(jq, 0), L - 1);
    const bool odd_valid = (pair >= 0 && pair < L);
    const int  lab       = targets[b * L + jc];
    bool skip = false;
    if (pair >= 1 && pair < 128) {
        const int oth = dir ? (jc + 1) : (jc - 1);
        skip = (targets[b * L + oth] != lab);
    }

    // loaders: tid<L -> label tid emission, tid==L -> blank
    const bool loader = (tid <= L);
    const float* gsrc = nullptr;
    unsigned dst0 = 0;
    if (loader) {
        const int vv = (tid < L) ? targets[b * L + tid] : 0;
        const int ee = (tid < L) ? (tid + 1)            : 0;
        gsrc = lp + (size_t)b * (size_t)V + vv;
        dst0 = smem_u32(&sh_e[0][ee]);
    }
    const size_t   strideT = (size_t)B * (size_t)V;
    const unsigned rowB    = EROW * sizeof(float);

    // emission time for step index k
    #define TOF(k) (dir ? (Tb - 1 - (k)) : (k))

    // prologue: groups for k = 0..23
    #pragma unroll
    for (int g = 0; g < 3; ++g) {
        if (loader) {
            #pragma unroll
            for (int i = 0; i < 8; ++i) {
                const int k = 8 * g + i;
                if (k <= N) cp4(dst0 + (unsigned)(k & (RSLOT - 1)) * rowB,
                                gsrc + (size_t)TOF(k) * strideT);
            }
        }
        cp_commit();
    }
    cp_wait2();
    __syncthreads();

    // init (k=0): fwd alpha(0) on states 0,1; bwd bt(Tb-1) on states 256,255
    float a_even = NEGV, a_odd = NEGV;
    if (pair == 0) { a_even = sh_e[0][0] * LOG2E; a_odd = sh_e[0][1 + jc] * LOG2E; }

    const int R = (N >> 3) + 1;
    for (int r = 0; r < R; ++r) {
        if (r > 0 && lane < HALO && pair >= 0) {
            a_even = sh_pa[(r - 1) & 1][pair];
            a_odd  = sh_po[(r - 1) & 1][pair];
        }

        float eb[8], el[8];
        #pragma unroll
        for (int i = 0; i < 8; ++i) {
            const int slot = (8 * r + i) & (RSLOT - 1);
            eb[i] = sh_e[slot][0];
            el[i] = sh_e[slot][1 + jc];
        }

        const int kg = 8 * (r + 3);
        #pragma unroll
        for (int i = 0; i < 8; ++i) {
            const int k = 8 * r + i;
            if (loader && (kg + i) <= N)
                cp4(dst0 + (unsigned)((kg + i) & (RSLOT - 1)) * rowB,
                    gsrc + (size_t)TOF(kg + i) * strideT);

            float po = __shfl_up_sync(0xFFFFFFFFu, a_odd, 1);
            if (pair == 0) po = NEGV;

            const float q = fmaxf(a_even, a_odd);
            const float m = fmaxf(q, po);
            const float x = ex2f(a_even - m);
            const float z = ex2f(a_odd  - m);
            const float y = ex2f(po     - m);

            float ne = fmaf(eb[i], LOG2E, m + lg2f(x + y));
            float no = fmaf(el[i], LOG2E, m + lg2f((x + z) + (skip ? y : 0.0f)));
            ne = fmaxf(ne, NEGV);
            no = fmaxf(no, NEGV);

            const bool live = (k >= 1) && (k <= N);
            a_even = live ? ne : a_even;
            a_odd  = live ? (odd_valid ? no : NEGV) : a_odd;
        }

        if (lane >= HALO && pair <= L) {
            sh_pa[r & 1][pair] = a_even;
            sh_po[r & 1][pair] = a_odd;
        }
        cp_commit();
        cp_wait2();
        __syncthreads();
    }

    if (dir) {
        // ---- backward: publish bt(tm+1, .) in natural state order ----
        if (lane >= HALO && pair <= 128) {
            const int qq = 127 - pair;                  // -1 .. 127
            if (qq >= 0) g_bt[b][2 * qq + 1] = a_odd;   // states 1,3,..,255
            g_bt[b][2 * qq + 2] = a_even;               // states 0,2,..,256
        }
        if (tid < 3) g_bt[b][257 + tid] = NEGV;
        __threadfence();
        __syncthreads();
        if (tid == 0) *((volatile int*)&g_flag[b]) = 1;
        return;
    }

    // ---- forward: wait for backward, merge tot = lse_s alpha(tm,s)+bb(tm,s) ----
    if (tid == 0) { while (*((volatile int*)&g_flag[b]) == 0) __nanosleep(32); }
    __syncthreads();
    __threadfence();

    float c = NEGV;
    const bool owner = (lane >= HALO) && (pair >= 0) && (pair <= 128);
    if (owner) {
        const float b0 = g_bt[b][2 * pair + 0];
        const float b1 = g_bt[b][2 * pair + 1];
        const float b2 = g_bt[b][2 * pair + 2];
        const float b3 = g_bt[b][2 * pair + 3];
        // s = 2p: succ {s, s+1}
        const float ve = a_even + lse2(b0, b1);
        // s = 2p+1: succ {s, s+1, s+2 if labels differ}
        float vo = NEGV;
        if (pair < 128) {
            const bool skipN = (pair + 1 < L) &&
                               (targets[b * L + pair + 1] != targets[b * L + pair]);
            float bbo = lse2(b1, b2);
            if (skipN) bbo = lse2(bbo, b3);
            vo = a_odd + bbo;
        }
        c = lse2(ve, vo);
    }
    // block lse-reduce (log2 domain), fixed order
    float mw = c;
    #pragma unroll
    for (int off = 16; off > 0; off >>= 1)
        mw = fmaxf(mw, __shfl_xor_sync(0xFFFFFFFFu, mw, off));
    float sw = owner ? ex2f(c - mw) : 0.0f;
    #pragma unroll
    for (int off = 16; off > 0; off >>= 1)
        sw += __shfl_xor_sync(0xFFFFFFFFu, sw, off);
    if (lane == 0) sh_red[w] = mw + lg2f(sw);
    __syncthreads();
    if (tid == 0) {
        float tot = sh_red[0];
        #pragma unroll
        for (int i = 1; i < NW; ++i) tot = lse2(tot, sh_red[i]);
        g_partial[b] = tot * LN2;
        *((volatile int*)&g_flag[b]) = 0;      // reset for next replay
    }

    // ---- deterministic final reduction: last forward CTA sums in fixed order ----
    __threadfence();
    __shared__ int s_last;
    if (tid == 0) s_last = (atomicAdd(&g_ctr, 1) == B - 1) ? 1 : 0;
    __syncthreads();
    if (s_last && w == 0) {
        __threadfence();
        float v = 0.0f;
        for (int i = lane; i < B; i += 32) v += g_partial[i];
        #pragma unroll
        for (int off = 16; off > 0; off >>= 1)
            v += __shfl_down_sync(0xFFFFFFFFu, v, off);
        if (lane == 0) { out[0] = -v; g_ctr = 0; }
    }
    #undef TOF
}

extern "C" void kernel_launch(void* const* d_in, const int* in_sizes, int n_in,
                              void* d_out, int out_size)
{
    const float* lp      = (const float*)d_in[0];   // log_probs [T,B,V] f32
    const int*   targets = (const int*)  d_in[1];   // [B*L] i32
    const int*   ilen    = (const int*)  d_in[2];   // [B] i32
    // d_in[3] = target_lengths (all == L), unused

    const int B = in_sizes[2];
    const int L = in_sizes[1] / B;
    const int V = 1000;                              // fixed problem shape
    const int T = (int)((long long)in_sizes[0] / ((long long)B * V));

    ctc_bidir<<<2 * B, BLOCK>>>(lp, targets, ilen, (float*)d_out, T, B, V, L);
}